// round 6
// baseline (speedup 1.0000x reference)
#include <cuda_runtime.h>
#include <math.h>

#define D 128
#define MAX_NODES 131072   // >= 100000 actual

// Per-node projections h[n]·Wu, h[n]·Wv. Separate arrays: each gather type
// pulls only the 4B it needs.
__device__ float g_pu[MAX_NODES];
__device__ float g_pv[MAX_NODES];

// ---------------------------------------------------------------------------
// Kernel 1: projections. 8 lanes per node, 4 nodes per warp.
// Measured at the 51.2 MB stream floor (~7.9us) — unchanged.
// ---------------------------------------------------------------------------
__global__ __launch_bounds__(256) void proj_kernel(
    const float* __restrict__ h,
    const float* __restrict__ W,   // [256]: Wu=W[0:128], Wv=W[128:256]
    int n_nodes)
{
    int lane = threadIdx.x & 31;
    int sub  = lane >> 3;
    int c    = lane & 7;

    const float4* Wu4 = reinterpret_cast<const float4*>(W);
    const float4* Wv4 = reinterpret_cast<const float4*>(W + D);
    float4 wu[4], wv[4];
    #pragma unroll
    for (int it = 0; it < 4; it++) {
        wu[it] = Wu4[it * 8 + c];
        wv[it] = Wv4[it * 8 + c];
    }

    int gwarp = (blockIdx.x * blockDim.x + threadIdx.x) >> 5;
    int node  = gwarp * 4 + sub;

    float su = 0.0f, sv = 0.0f;
    if (node < n_nodes) {
        const float4* hp = reinterpret_cast<const float4*>(h + (size_t)node * D);
        float4 hv[4];
        #pragma unroll
        for (int it = 0; it < 4; it++)
            hv[it] = __ldcs(&hp[it * 8 + c]);
        #pragma unroll
        for (int it = 0; it < 4; it++) {
            su += hv[it].x * wu[it].x + hv[it].y * wu[it].y
                + hv[it].z * wu[it].z + hv[it].w * wu[it].w;
            sv += hv[it].x * wv[it].x + hv[it].y * wv[it].y
                + hv[it].z * wv[it].z + hv[it].w * wv[it].w;
        }
    }

    #pragma unroll
    for (int o = 4; o >= 1; o >>= 1) {
        su += __shfl_xor_sync(0xFFFFFFFFu, su, o);
        sv += __shfl_xor_sync(0xFFFFFFFFu, sv, o);
    }
    if (c == 0 && node < n_nodes) {
        g_pu[node] = su;
        g_pv[node] = sv;
    }
}

// ---------------------------------------------------------------------------
// Kernel 2: per-edge score, 8 edges per thread, 128-thread blocks.
// Geometry: 1563 blocks = 10.6 blocks/SM avg; launch_bounds(128,11) caps regs
// at 46 so the residency ceiling (>=11 blocks/SM) exceeds the grid -> single
// wave, no tail, ~2x outstanding gathers per warp vs the 4-edge variant.
//  - gathers via __ldcg (L2-only): skips L1 allocate/fill work on the
//    bottleneck l1tex pipe; L1 temporal reuse on the tables is ~10% anyway
//  - index loads / output stores .cs: 19.2 MB of streams must not evict the
//    800 KB L2-resident pu/pv tables
//  - all 16 gathers issued before any dependent math
// ---------------------------------------------------------------------------
__global__ __launch_bounds__(128, 11) void edge_kernel8(
    const int*  __restrict__ src,
    const int*  __restrict__ dst,
    const float* __restrict__ bias,
    float* __restrict__ out,
    int n_oct)                     // total_edges / 8
{
    int i = blockIdx.x * blockDim.x + threadIdx.x;
    if (i >= n_oct) return;

    float b = __ldg(bias);
    const int4* s4 = reinterpret_cast<const int4*>(src);
    const int4* d4 = reinterpret_cast<const int4*>(dst);

    int4 s0 = __ldcs(&s4[2 * i]);
    int4 s1 = __ldcs(&s4[2 * i + 1]);
    int4 d0 = __ldcs(&d4[2 * i]);
    int4 d1 = __ldcs(&d4[2 * i + 1]);

    // All 16 gathers in flight before dependent math
    float u0 = __ldcg(&g_pu[s0.x]), u1 = __ldcg(&g_pu[s0.y]);
    float u2 = __ldcg(&g_pu[s0.z]), u3 = __ldcg(&g_pu[s0.w]);
    float u4 = __ldcg(&g_pu[s1.x]), u5 = __ldcg(&g_pu[s1.y]);
    float u6 = __ldcg(&g_pu[s1.z]), u7 = __ldcg(&g_pu[s1.w]);
    float v0 = __ldcg(&g_pv[d0.x]), v1 = __ldcg(&g_pv[d0.y]);
    float v2 = __ldcg(&g_pv[d0.z]), v3 = __ldcg(&g_pv[d0.w]);
    float v4 = __ldcg(&g_pv[d1.x]), v5 = __ldcg(&g_pv[d1.y]);
    float v6 = __ldcg(&g_pv[d1.z]), v7 = __ldcg(&g_pv[d1.w]);

    float4 o0, o1;
    o0.x = 1.0f / (1.0f + __expf(-(u0 + v0 + b)));
    o0.y = 1.0f / (1.0f + __expf(-(u1 + v1 + b)));
    o0.z = 1.0f / (1.0f + __expf(-(u2 + v2 + b)));
    o0.w = 1.0f / (1.0f + __expf(-(u3 + v3 + b)));
    o1.x = 1.0f / (1.0f + __expf(-(u4 + v4 + b)));
    o1.y = 1.0f / (1.0f + __expf(-(u5 + v5 + b)));
    o1.z = 1.0f / (1.0f + __expf(-(u6 + v6 + b)));
    o1.w = 1.0f / (1.0f + __expf(-(u7 + v7 + b)));

    float4* o4 = reinterpret_cast<float4*>(out);
    __stcs(&o4[2 * i],     o0);
    __stcs(&o4[2 * i + 1], o1);
}

// Scalar tail (unused when n_edges % 8 == 0; 1.6M % 8 == 0)
__global__ void edge_kernel_tail(
    const int*  __restrict__ src,
    const int*  __restrict__ dst,
    const float* __restrict__ bias,
    float* __restrict__ out,
    int start, int n_edges)
{
    int i = start + blockIdx.x * blockDim.x + threadIdx.x;
    if (i >= n_edges) return;
    float x = g_pu[src[i]] + g_pv[dst[i]] + bias[0];
    out[i] = 1.0f / (1.0f + __expf(-x));
}

extern "C" void kernel_launch(void* const* d_in, const int* in_sizes, int n_in,
                              void* d_out, int out_size)
{
    const float* h      = (const float*)d_in[0];
    const int*   src    = (const int*)  d_in[1];
    const int*   dst    = (const int*)  d_in[2];
    const float* W      = (const float*)d_in[3];
    const float* W_bias = (const float*)d_in[4];
    float* out          = (float*)d_out;

    int n_nodes = in_sizes[0] / D;
    int n_edges = in_sizes[1];

    // Kernel 1: 4 nodes per warp
    {
        int n_groups = (n_nodes + 3) / 4;
        int blocks = (n_groups * 32 + 255) / 256;
        proj_kernel<<<blocks, 256>>>(h, W, n_nodes);
    }

    // Kernel 2: 8 edges per thread, 128-thread blocks -> single wave
    {
        int n_oct = n_edges / 8;
        if (n_oct > 0) {
            int blocks = (n_oct + 127) / 128;
            edge_kernel8<<<blocks, 128>>>(src, dst, W_bias, out, n_oct);
        }
        int tail_start = n_oct * 8;
        int tail = n_edges - tail_start;
        if (tail > 0)
            edge_kernel_tail<<<(tail + 255) / 256, 256>>>(src, dst, W_bias, out,
                                                          tail_start, n_edges);
    }
}

// round 7
// speedup vs baseline: 1.0071x; 1.0071x over previous
#include <cuda_runtime.h>
#include <math.h>

#define D 128
#define MAX_NODES 131072   // >= 100000 actual

// Per-node projections h[n]·Wu, h[n]·Wv. Separate arrays: each gather type
// pulls only the 4B it needs.
__device__ float g_pu[MAX_NODES];
__device__ float g_pv[MAX_NODES];

// ---------------------------------------------------------------------------
// Kernel 1: projections. 8 lanes per node, 4 nodes per warp.
// Measured at the 51.2 MB stream floor (~7.9us) — unchanged since R3.
// ---------------------------------------------------------------------------
__global__ __launch_bounds__(256) void proj_kernel(
    const float* __restrict__ h,
    const float* __restrict__ W,   // [256]: Wu=W[0:128], Wv=W[128:256]
    int n_nodes)
{
    int lane = threadIdx.x & 31;
    int sub  = lane >> 3;
    int c    = lane & 7;

    const float4* Wu4 = reinterpret_cast<const float4*>(W);
    const float4* Wv4 = reinterpret_cast<const float4*>(W + D);
    float4 wu[4], wv[4];
    #pragma unroll
    for (int it = 0; it < 4; it++) {
        wu[it] = Wu4[it * 8 + c];
        wv[it] = Wv4[it * 8 + c];
    }

    int gwarp = (blockIdx.x * blockDim.x + threadIdx.x) >> 5;
    int node  = gwarp * 4 + sub;

    float su = 0.0f, sv = 0.0f;
    if (node < n_nodes) {
        const float4* hp = reinterpret_cast<const float4*>(h + (size_t)node * D);
        float4 hv[4];
        #pragma unroll
        for (int it = 0; it < 4; it++)
            hv[it] = __ldcs(&hp[it * 8 + c]);   // h is streamed exactly once
        #pragma unroll
        for (int it = 0; it < 4; it++) {
            su += hv[it].x * wu[it].x + hv[it].y * wu[it].y
                + hv[it].z * wu[it].z + hv[it].w * wu[it].w;
            sv += hv[it].x * wv[it].x + hv[it].y * wv[it].y
                + hv[it].z * wv[it].z + hv[it].w * wv[it].w;
        }
    }

    #pragma unroll
    for (int o = 4; o >= 1; o >>= 1) {
        su += __shfl_xor_sync(0xFFFFFFFFu, su, o);
        sv += __shfl_xor_sync(0xFFFFFFFFu, sv, o);
    }
    if (c == 0 && node < n_nodes) {
        g_pu[node] = su;
        g_pv[node] = sv;
    }
}

// ---------------------------------------------------------------------------
// Kernel 2: per-edge score — the empirically fastest shape (R2: 16.29us,
// 4 edges/thread, 256-thr blocks, regs 28, occ 72%). Do NOT widen per-thread
// work: both 8-edge variants regressed (R3, R6) at identical L1 utilization.
// Only delta vs R2: cache policy —
//  - gathers __ldcg (L2-only): tables (800 KB) >> L1 (228 KB) under random
//    access, so L1 allocation is pure overhead on the bottleneck l1tex pipe
//  - index loads / stores .cs: 19.2 MB of streams must not evict the
//    L2-resident pu/pv tables
// ---------------------------------------------------------------------------
__global__ __launch_bounds__(256) void edge_kernel(
    const int*  __restrict__ src,
    const int*  __restrict__ dst,
    const float* __restrict__ bias,
    float* __restrict__ out,
    int n_quads)                   // total_edges / 4
{
    int i = blockIdx.x * blockDim.x + threadIdx.x;
    if (i >= n_quads) return;

    float b = __ldg(bias);
    int4 s = __ldcs(&reinterpret_cast<const int4*>(src)[i]);
    int4 d = __ldcs(&reinterpret_cast<const int4*>(dst)[i]);

    // All 8 gathers in flight before any dependent math
    float u0 = __ldcg(&g_pu[s.x]), u1 = __ldcg(&g_pu[s.y]);
    float u2 = __ldcg(&g_pu[s.z]), u3 = __ldcg(&g_pu[s.w]);
    float v0 = __ldcg(&g_pv[d.x]), v1 = __ldcg(&g_pv[d.y]);
    float v2 = __ldcg(&g_pv[d.z]), v3 = __ldcg(&g_pv[d.w]);

    float4 o;
    o.x = 1.0f / (1.0f + __expf(-(u0 + v0 + b)));
    o.y = 1.0f / (1.0f + __expf(-(u1 + v1 + b)));
    o.z = 1.0f / (1.0f + __expf(-(u2 + v2 + b)));
    o.w = 1.0f / (1.0f + __expf(-(u3 + v3 + b)));

    __stcs(&reinterpret_cast<float4*>(out)[i], o);
}

// Scalar tail (unused when n_edges % 4 == 0; 1.6M % 4 == 0)
__global__ void edge_kernel_tail(
    const int*  __restrict__ src,
    const int*  __restrict__ dst,
    const float* __restrict__ bias,
    float* __restrict__ out,
    int start, int n_edges)
{
    int i = start + blockIdx.x * blockDim.x + threadIdx.x;
    if (i >= n_edges) return;
    float x = g_pu[src[i]] + g_pv[dst[i]] + bias[0];
    out[i] = 1.0f / (1.0f + __expf(-x));
}

extern "C" void kernel_launch(void* const* d_in, const int* in_sizes, int n_in,
                              void* d_out, int out_size)
{
    const float* h      = (const float*)d_in[0];
    const int*   src    = (const int*)  d_in[1];
    const int*   dst    = (const int*)  d_in[2];
    const float* W      = (const float*)d_in[3];
    const float* W_bias = (const float*)d_in[4];
    float* out          = (float*)d_out;

    int n_nodes = in_sizes[0] / D;
    int n_edges = in_sizes[1];

    // Kernel 1: 4 nodes per warp
    {
        int n_groups = (n_nodes + 3) / 4;
        int blocks = (n_groups * 32 + 255) / 256;
        proj_kernel<<<blocks, 256>>>(h, W, n_nodes);
    }

    // Kernel 2: 4 edges per thread, 256-thread blocks (R2 geometry)
    {
        int n_quads = n_edges / 4;
        if (n_quads > 0) {
            int blocks = (n_quads + 255) / 256;
            edge_kernel<<<blocks, 256>>>(src, dst, W_bias, out, n_quads);
        }
        int tail_start = n_quads * 4;
        int tail = n_edges - tail_start;
        if (tail > 0)
            edge_kernel_tail<<<(tail + 255) / 256, 256>>>(src, dst, W_bias, out,
                                                          tail_start, n_edges);
    }
}

// round 8
// speedup vs baseline: 1.0759x; 1.0684x over previous
#include <cuda_runtime.h>
#include <math.h>

#define D 128
#define MAX_NODES 131072   // >= 100000 actual

// Per-node projections h[n]·Wu, h[n]·Wv.
__device__ float g_pu[MAX_NODES];
__device__ float g_pv[MAX_NODES];

// ---------------------------------------------------------------------------
// Kernel 1: projections. 8 lanes per node, 4 nodes per warp.
// Measured at the 51.2 MB stream floor (~7.9us). Unchanged since R3.
// ---------------------------------------------------------------------------
__global__ __launch_bounds__(256) void proj_kernel(
    const float* __restrict__ h,
    const float* __restrict__ W,   // [256]: Wu=W[0:128], Wv=W[128:256]
    int n_nodes)
{
    int lane = threadIdx.x & 31;
    int sub  = lane >> 3;
    int c    = lane & 7;

    const float4* Wu4 = reinterpret_cast<const float4*>(W);
    const float4* Wv4 = reinterpret_cast<const float4*>(W + D);
    float4 wu[4], wv[4];
    #pragma unroll
    for (int it = 0; it < 4; it++) {
        wu[it] = Wu4[it * 8 + c];
        wv[it] = Wv4[it * 8 + c];
    }

    int gwarp = (blockIdx.x * blockDim.x + threadIdx.x) >> 5;
    int node  = gwarp * 4 + sub;

    float su = 0.0f, sv = 0.0f;
    if (node < n_nodes) {
        const float4* hp = reinterpret_cast<const float4*>(h + (size_t)node * D);
        float4 hv[4];
        #pragma unroll
        for (int it = 0; it < 4; it++)
            hv[it] = __ldcs(&hp[it * 8 + c]);   // h streamed exactly once
        #pragma unroll
        for (int it = 0; it < 4; it++) {
            su += hv[it].x * wu[it].x + hv[it].y * wu[it].y
                + hv[it].z * wu[it].z + hv[it].w * wu[it].w;
            sv += hv[it].x * wv[it].x + hv[it].y * wv[it].y
                + hv[it].z * wv[it].z + hv[it].w * wv[it].w;
        }
    }

    #pragma unroll
    for (int o = 4; o >= 1; o >>= 1) {
        su += __shfl_xor_sync(0xFFFFFFFFu, su, o);
        sv += __shfl_xor_sync(0xFFFFFFFFu, sv, o);
    }
    if (c == 0 && node < n_nodes) {
        g_pu[node] = su;
        g_pv[node] = sv;
    }
}

// ---------------------------------------------------------------------------
// Kernel 2: per-edge score — byte-exact R2 shape, the fastest measured
// (16.29us, regs 28, occ 72.4%). Plain loads everywhere: R7 proved .cg on
// gathers costs ~1.4us (L1 hits on the tables are real), R5 suggested .cs on
// streams costs ~0.6us. No cache hints, 4 edges/thread, 256-thread blocks.
// ---------------------------------------------------------------------------
__global__ __launch_bounds__(256) void edge_kernel(
    const int*  __restrict__ src,
    const int*  __restrict__ dst,
    const float* __restrict__ bias,
    float* __restrict__ out,
    int n_quads)                   // total_edges / 4
{
    int i = blockIdx.x * blockDim.x + threadIdx.x;
    if (i >= n_quads) return;

    float b = bias[0];
    int4 s = reinterpret_cast<const int4*>(src)[i];
    int4 d = reinterpret_cast<const int4*>(dst)[i];

    // All 8 gathers issued before any dependent math
    float u0 = g_pu[s.x], u1 = g_pu[s.y], u2 = g_pu[s.z], u3 = g_pu[s.w];
    float v0 = g_pv[d.x], v1 = g_pv[d.y], v2 = g_pv[d.z], v3 = g_pv[d.w];

    float x0 = u0 + v0 + b;
    float x1 = u1 + v1 + b;
    float x2 = u2 + v2 + b;
    float x3 = u3 + v3 + b;

    float4 o;
    o.x = 1.0f / (1.0f + expf(-x0));
    o.y = 1.0f / (1.0f + expf(-x1));
    o.z = 1.0f / (1.0f + expf(-x2));
    o.w = 1.0f / (1.0f + expf(-x3));

    reinterpret_cast<float4*>(out)[i] = o;
}

// Scalar tail (unused when n_edges % 4 == 0; 1.6M % 4 == 0)
__global__ void edge_kernel_tail(
    const int*  __restrict__ src,
    const int*  __restrict__ dst,
    const float* __restrict__ bias,
    float* __restrict__ out,
    int start, int n_edges)
{
    int i = start + blockIdx.x * blockDim.x + threadIdx.x;
    if (i >= n_edges) return;
    float x = g_pu[src[i]] + g_pv[dst[i]] + bias[0];
    out[i] = 1.0f / (1.0f + expf(-x));
}

extern "C" void kernel_launch(void* const* d_in, const int* in_sizes, int n_in,
                              void* d_out, int out_size)
{
    const float* h      = (const float*)d_in[0];
    const int*   src    = (const int*)  d_in[1];
    const int*   dst    = (const int*)  d_in[2];
    const float* W      = (const float*)d_in[3];
    const float* W_bias = (const float*)d_in[4];
    float* out          = (float*)d_out;

    int n_nodes = in_sizes[0] / D;
    int n_edges = in_sizes[1];

    // Kernel 1: 4 nodes per warp
    {
        int n_groups = (n_nodes + 3) / 4;
        int blocks = (n_groups * 32 + 255) / 256;
        proj_kernel<<<blocks, 256>>>(h, W, n_nodes);
    }

    // Kernel 2: 4 edges per thread, 256-thread blocks (R2 geometry, R2 code)
    {
        int n_quads = n_edges / 4;
        if (n_quads > 0) {
            int blocks = (n_quads + 255) / 256;
            edge_kernel<<<blocks, 256>>>(src, dst, W_bias, out, n_quads);
        }
        int tail_start = n_quads * 4;
        int tail = n_edges - tail_start;
        if (tail > 0)
            edge_kernel_tail<<<(tail + 255) / 256, 256>>>(src, dst, W_bias, out,
                                                          tail_start, n_edges);
    }
}

// round 10
// speedup vs baseline: 1.0842x; 1.0077x over previous
#include <cuda_runtime.h>
#include <cuda_fp16.h>
#include <math.h>

#define D 128
#define MAX_NODES 131072   // >= 100000 actual

// Per-node projections in fp16: halves table footprint (800KB -> 400KB),
// nearly fitting L1 (228KB/SM) -> ~2x L1 hit rate on the random gathers.
// Precision: |p| ~ 0.5, fp16 rel err 4.9e-4 -> output rel err ~1.5e-4 << 1e-3.
__device__ __half g_pu[MAX_NODES];
__device__ __half g_pv[MAX_NODES];

// ---------------------------------------------------------------------------
// Kernel 1: projections. 8 lanes per node, 4 nodes per warp.
// Measured at the HBM stream roofline (~6.5 TB/s). Only delta: fp16 writes.
// ---------------------------------------------------------------------------
__global__ __launch_bounds__(256) void proj_kernel(
    const float* __restrict__ h,
    const float* __restrict__ W,   // [256]: Wu=W[0:128], Wv=W[128:256]
    int n_nodes)
{
    int lane = threadIdx.x & 31;
    int sub  = lane >> 3;
    int c    = lane & 7;

    const float4* Wu4 = reinterpret_cast<const float4*>(W);
    const float4* Wv4 = reinterpret_cast<const float4*>(W + D);
    float4 wu[4], wv[4];
    #pragma unroll
    for (int it = 0; it < 4; it++) {
        wu[it] = Wu4[it * 8 + c];
        wv[it] = Wv4[it * 8 + c];
    }

    int gwarp = (blockIdx.x * blockDim.x + threadIdx.x) >> 5;
    int node  = gwarp * 4 + sub;

    float su = 0.0f, sv = 0.0f;
    if (node < n_nodes) {
        const float4* hp = reinterpret_cast<const float4*>(h + (size_t)node * D);
        float4 hv[4];
        #pragma unroll
        for (int it = 0; it < 4; it++)
            hv[it] = __ldcs(&hp[it * 8 + c]);   // h streamed exactly once
        #pragma unroll
        for (int it = 0; it < 4; it++) {
            su += hv[it].x * wu[it].x + hv[it].y * wu[it].y
                + hv[it].z * wu[it].z + hv[it].w * wu[it].w;
            sv += hv[it].x * wv[it].x + hv[it].y * wv[it].y
                + hv[it].z * wv[it].z + hv[it].w * wv[it].w;
        }
    }

    #pragma unroll
    for (int o = 4; o >= 1; o >>= 1) {
        su += __shfl_xor_sync(0xFFFFFFFFu, su, o);
        sv += __shfl_xor_sync(0xFFFFFFFFu, sv, o);
    }
    if (c == 0 && node < n_nodes) {
        g_pu[node] = __float2half(su);
        g_pv[node] = __float2half(sv);
    }
}

// ---------------------------------------------------------------------------
// Kernel 2: per-edge score. Proven shape (4 edges/thread, 256-thr blocks,
// plain loads — R2/R8: 16.3-16.5us), plus two orthogonal deltas:
//  - fp16 table gathers (higher L1 hit rate -> shorter average latency)
//  - single-wave grid-stride (1184 blocks = 8/SM x 148 SMs): no wave tail;
//    ~32% of threads run a second quad, spread evenly across SMs.
// ---------------------------------------------------------------------------
__global__ __launch_bounds__(256) void edge_kernel(
    const int*  __restrict__ src,
    const int*  __restrict__ dst,
    const float* __restrict__ bias,
    float* __restrict__ out,
    int n_quads)                   // total_edges / 4
{
    int stride = gridDim.x * blockDim.x;
    float b = bias[0];

    for (int i = blockIdx.x * blockDim.x + threadIdx.x; i < n_quads; i += stride) {
        int4 s = reinterpret_cast<const int4*>(src)[i];
        int4 d = reinterpret_cast<const int4*>(dst)[i];

        // All 8 gathers issued before any dependent math
        float u0 = __half2float(g_pu[s.x]);
        float u1 = __half2float(g_pu[s.y]);
        float u2 = __half2float(g_pu[s.z]);
        float u3 = __half2float(g_pu[s.w]);
        float v0 = __half2float(g_pv[d.x]);
        float v1 = __half2float(g_pv[d.y]);
        float v2 = __half2float(g_pv[d.z]);
        float v3 = __half2float(g_pv[d.w]);

        float4 o;
        o.x = 1.0f / (1.0f + expf(-(u0 + v0 + b)));
        o.y = 1.0f / (1.0f + expf(-(u1 + v1 + b)));
        o.z = 1.0f / (1.0f + expf(-(u2 + v2 + b)));
        o.w = 1.0f / (1.0f + expf(-(u3 + v3 + b)));

        reinterpret_cast<float4*>(out)[i] = o;
    }
}

// Scalar tail (unused when n_edges % 4 == 0; 1.6M % 4 == 0)
__global__ void edge_kernel_tail(
    const int*  __restrict__ src,
    const int*  __restrict__ dst,
    const float* __restrict__ bias,
    float* __restrict__ out,
    int start, int n_edges)
{
    int i = start + blockIdx.x * blockDim.x + threadIdx.x;
    if (i >= n_edges) return;
    float x = __half2float(g_pu[src[i]]) + __half2float(g_pv[dst[i]]) + bias[0];
    out[i] = 1.0f / (1.0f + expf(-x));
}

extern "C" void kernel_launch(void* const* d_in, const int* in_sizes, int n_in,
                              void* d_out, int out_size)
{
    const float* h      = (const float*)d_in[0];
    const int*   src    = (const int*)  d_in[1];
    const int*   dst    = (const int*)  d_in[2];
    const float* W      = (const float*)d_in[3];
    const float* W_bias = (const float*)d_in[4];
    float* out          = (float*)d_out;

    int n_nodes = in_sizes[0] / D;
    int n_edges = in_sizes[1];

    // Kernel 1: 4 nodes per warp
    {
        int n_groups = (n_nodes + 3) / 4;
        int blocks = (n_groups * 32 + 255) / 256;
        proj_kernel<<<blocks, 256>>>(h, W, n_nodes);
    }

    // Kernel 2: single wave of 1184 blocks (8 blocks/SM x 148 SMs),
    // grid-stride over quads
    {
        int n_quads = n_edges / 4;
        if (n_quads > 0) {
            int blocks = 1184;
            int max_needed = (n_quads + 255) / 256;
            if (blocks > max_needed) blocks = max_needed;
            edge_kernel<<<blocks, 256>>>(src, dst, W_bias, out, n_quads);
        }
        int tail_start = n_quads * 4;
        int tail = n_edges - tail_start;
        if (tail > 0)
            edge_kernel_tail<<<(tail + 255) / 256, 256>>>(src, dst, W_bias, out,
                                                          tail_start, n_edges);
    }
}